// round 10
// baseline (speedup 1.0000x reference)
#include <cuda_runtime.h>

// Bernstein flow density, DIM=5, TF_DEG=16, COND_DEG=3, N=262144.
// Table: C0:1, C1:4, C2:16, C3:64, C4:256 => 341 rows x 15 cols (padded to 16).
// R10: R3 structure (best: 69.2us) + __launch_bounds__(128,5) for 20 warps/SM.
#define NROWS 341
#define O1 1
#define O2 5
#define O3 21
#define O4 85
#define BLK 128

typedef unsigned long long u64;

__device__ __align__(16) float gC[NROWS * 16];

__device__ __forceinline__ float softplusf(float a) {
    return fmaxf(a, 0.0f) + log1pf(expf(-fabsf(a)));
}

// constrained(A): 2*(sigmoid(cumsum(softplus(A),axis=1)) - 0.5) == tanh(cumsum/2)
__global__ void prep_kernel(const float* __restrict__ A0, const float* __restrict__ A1,
                            const float* __restrict__ A2, const float* __restrict__ A3,
                            const float* __restrict__ A4) {
    int r = blockIdx.x * blockDim.x + threadIdx.x;
    if (r >= NROWS) return;
    const float* A; int lr;
    if (r < O1)      { A = A0; lr = r; }
    else if (r < O2) { A = A1; lr = r - O1; }
    else if (r < O3) { A = A2; lr = r - O2; }
    else if (r < O4) { A = A3; lr = r - O3; }
    else             { A = A4; lr = r - O4; }
    float s = 0.0f;
    #pragma unroll
    for (int t = 0; t < 15; t++) {
        s += softplusf(A[lr * 15 + t]);
        gC[r * 16 + t] = tanhf(0.5f * s);
    }
    gC[r * 16 + 15] = 0.0f;
}

// ---- f32x2 helpers ----
__device__ __forceinline__ u64 pack2(float c) {
    u64 r;
    asm("mov.b64 %0, {%1, %1};" : "=l"(r) : "r"(__float_as_uint(c)));
    return r;
}
__device__ __forceinline__ u64 pack_pair(float lo, float hi) {
    u64 r;
    asm("mov.b64 %0, {%1, %2};" : "=l"(r) : "r"(__float_as_uint(lo)), "r"(__float_as_uint(hi)));
    return r;
}
__device__ __forceinline__ void unpack2(float& lo, float& hi, u64 v) {
    unsigned a, b;
    asm("mov.b64 {%0, %1}, %2;" : "=r"(a), "=r"(b) : "l"(v));
    lo = __uint_as_float(a); hi = __uint_as_float(b);
}
__device__ __forceinline__ void ffma2(u64& d, u64 a, u64 b) {
    asm("fma.rn.f32x2 %0, %1, %2, %0;" : "+l"(d) : "l"(a), "l"(b));
}

__device__ __forceinline__ void bern3(float x, float b[4]) {
    float om = 1.0f - x;
    b[0] = om * om * om;
    b[1] = 3.0f * x * om * om;
    b[2] = 3.0f * x * x * om;
    b[3] = x * x * x;
}

// S = db[15] + sum_{t<15} tf[t]*(db[t]-db[t+1]),  db[t] = 16*C(15,t)*x^t*(1-x)^(15-t)
__device__ __forceinline__ float stage_S(const float tf[16], float xi) {
    const float comb15[16] = {1.f, 15.f, 105.f, 455.f, 1365.f, 3003.f, 5005.f, 6435.f,
                              6435.f, 5005.f, 3003.f, 1365.f, 455.f, 105.f, 15.f, 1.f};
    float db[16];
    float om = 1.0f - xi;
    float p = 16.0f;
    #pragma unroll
    for (int t = 0; t < 16; t++) { db[t] = p * comb15[t]; p *= xi; }
    p = 1.0f;
    #pragma unroll
    for (int t = 15; t >= 0; t--) { db[t] *= p; p *= om; }
    float s = db[15];
    #pragma unroll
    for (int t = 0; t < 15; t++) s = fmaf(tf[t], db[t] - db[t + 1], s);
    return s;
}

__device__ __forceinline__ float stage_S_u(const u64 t2[8], float xi) {
    float tf[16];
    #pragma unroll
    for (int i = 0; i < 8; i++) unpack2(tf[2 * i], tf[2 * i + 1], t2[i]);
    return stage_S(tf, xi);
}

// tf_a/tf_b += c_a/c_b * row[0..15]  (row: 16 floats = 8 u64, via 4x ld.shared.v2.b64)
__device__ __forceinline__ void acc_row2(u64 tfa[8], u64 tfb[8], float ca, float cb,
                                         const float* __restrict__ row) {
    u64 r0, r1, r2, r3, r4, r5, r6, r7;
    size_t p = __cvta_generic_to_shared(row);
    asm("ld.shared.v2.b64 {%0, %1}, [%2];"      : "=l"(r0), "=l"(r1) : "l"(p));
    asm("ld.shared.v2.b64 {%0, %1}, [%2 + 16];" : "=l"(r2), "=l"(r3) : "l"(p));
    asm("ld.shared.v2.b64 {%0, %1}, [%2 + 32];" : "=l"(r4), "=l"(r5) : "l"(p));
    asm("ld.shared.v2.b64 {%0, %1}, [%2 + 48];" : "=l"(r6), "=l"(r7) : "l"(p));
    u64 cca = pack2(ca), ccb = pack2(cb);
    ffma2(tfa[0], cca, r0); ffma2(tfa[1], cca, r1);
    ffma2(tfa[2], cca, r2); ffma2(tfa[3], cca, r3);
    ffma2(tfa[4], cca, r4); ffma2(tfa[5], cca, r5);
    ffma2(tfa[6], cca, r6); ffma2(tfa[7], cca, r7);
    ffma2(tfb[0], ccb, r0); ffma2(tfb[1], ccb, r1);
    ffma2(tfb[2], ccb, r2); ffma2(tfb[3], ccb, r3);
    ffma2(tfb[4], ccb, r4); ffma2(tfb[5], ccb, r5);
    ffma2(tfb[6], ccb, r6); ffma2(tfb[7], ccb, r7);
}

__global__ __launch_bounds__(BLK, 5)
void bflow_kernel(const float* __restrict__ x, float* __restrict__ out, int n) {
    __shared__ __align__(16) float sC[NROWS * 16];
    __shared__ u64 sCB2[16][BLK];   // packed (cb2 of point a, cb2 of point b)

    {   // stage the coefficient table into SMEM
        const float4* src = (const float4*)gC;
        float4* dst = (float4*)sC;
        for (int i = threadIdx.x; i < NROWS * 4; i += BLK) dst[i] = src[i];
    }
    __syncthreads();

    int base = blockIdx.x * (BLK * 2);
    int ia = base + threadIdx.x;
    int ib = ia + BLK;
    bool va = ia < n, vb = ib < n;
    int ra = va ? ia : 0, rb = vb ? ib : 0;

    float xa[5], xb[5];
    #pragma unroll
    for (int j = 0; j < 5; j++) { xa[j] = x[ra * 5 + j]; xb[j] = x[rb * 5 + j]; }

    float dens_a, dens_b;
    u64 ta[8], tb[8];

    // ---- stage 0: cb = [1] (same tf for both points) ----
    {
        float tf[16];
        #pragma unroll
        for (int t = 0; t < 16; t++) tf[t] = sC[t];
        dens_a = stage_S(tf, xa[0]);
        dens_b = stage_S(tf, xb[0]);
    }

    float Ba0[4], Bb0[4]; bern3(xa[0], Ba0); bern3(xb[0], Bb0);

    // ---- stage 1: cb = B0 ----
    #pragma unroll
    for (int i = 0; i < 8; i++) { ta[i] = 0ull; tb[i] = 0ull; }
    #pragma unroll
    for (int k = 0; k < 4; k++)
        acc_row2(ta, tb, Ba0[k], Bb0[k], sC + (O1 + k) * 16);
    dens_a *= stage_S_u(ta, xa[1]);
    dens_b *= stage_S_u(tb, xb[1]);

    float Ba1[4], Bb1[4]; bern3(xa[1], Ba1); bern3(xb[1], Bb1);

    // ---- stage 2: cb2 = B0 (x) B1; also store packed cb2 to SMEM ----
    #pragma unroll
    for (int i = 0; i < 8; i++) { ta[i] = 0ull; tb[i] = 0ull; }
    #pragma unroll
    for (int m = 0; m < 4; m++)
        #pragma unroll
        for (int k = 0; k < 4; k++) {
            float c2a = Ba0[m] * Ba1[k];
            float c2b = Bb0[m] * Bb1[k];
            sCB2[m * 4 + k][threadIdx.x] = pack_pair(c2a, c2b);
            acc_row2(ta, tb, c2a, c2b, sC + (O2 + m * 4 + k) * 16);
        }
    dens_a *= stage_S_u(ta, xa[2]);
    dens_b *= stage_S_u(tb, xb[2]);

    float Ba2[4], Bb2[4]; bern3(xa[2], Ba2); bern3(xb[2], Bb2);

    // ---- stage 3: cb3[m*4+k] = cb2[m]*B2[k], rolled outer loop ----
    #pragma unroll
    for (int i = 0; i < 8; i++) { ta[i] = 0ull; tb[i] = 0ull; }
    #pragma unroll 1
    for (int m = 0; m < 16; m++) {
        float c2a, c2b; unpack2(c2a, c2b, sCB2[m][threadIdx.x]);
        const float* bp = sC + (O3 + m * 4) * 16;
        #pragma unroll
        for (int k = 0; k < 4; k++)
            acc_row2(ta, tb, c2a * Ba2[k], c2b * Bb2[k], bp + k * 16);
    }
    dens_a *= stage_S_u(ta, xa[3]);
    dens_b *= stage_S_u(tb, xb[3]);

    float Ba3[4], Bb3[4]; bern3(xa[3], Ba3); bern3(xb[3], Bb3);

    // ---- stage 4: cb4[(m*4+k2)*4+k3] = cb2[m]*B2[k2]*B3[k3], rolled outer loop ----
    #pragma unroll
    for (int i = 0; i < 8; i++) { ta[i] = 0ull; tb[i] = 0ull; }
    #pragma unroll 1
    for (int m = 0; m < 16; m++) {
        float c2a, c2b; unpack2(c2a, c2b, sCB2[m][threadIdx.x]);
        const float* bp = sC + (O4 + m * 16) * 16;
        #pragma unroll
        for (int k2 = 0; k2 < 4; k2++) {
            float c3a = c2a * Ba2[k2];
            float c3b = c2b * Bb2[k2];
            #pragma unroll
            for (int k3 = 0; k3 < 4; k3++)
                acc_row2(ta, tb, c3a * Ba3[k3], c3b * Bb3[k3], bp + (k2 * 4 + k3) * 16);
        }
    }
    dens_a *= stage_S_u(ta, xa[4]);
    dens_b *= stage_S_u(tb, xb[4]);

    if (va) out[ia] = dens_a;
    if (vb) out[ib] = dens_b;
}

extern "C" void kernel_launch(void* const* d_in, const int* in_sizes, int n_in,
                              void* d_out, int out_size) {
    const float* x  = (const float*)d_in[0];
    const float* A0 = (const float*)d_in[1];
    const float* A1 = (const float*)d_in[2];
    const float* A2 = (const float*)d_in[3];
    const float* A3 = (const float*)d_in[4];
    const float* A4 = (const float*)d_in[5];
    float* out = (float*)d_out;
    int n = in_sizes[0] / 5;

    prep_kernel<<<(NROWS + 127) / 128, 128>>>(A0, A1, A2, A3, A4);
    int pts_per_blk = BLK * 2;
    bflow_kernel<<<(n + pts_per_blk - 1) / pts_per_blk, BLK>>>(x, out, n);
}

// round 12
// speedup vs baseline: 1.4062x; 1.4062x over previous
#include <cuda_runtime.h>

// Bernstein flow density, DIM=5, TF_DEG=16, COND_DEG=3, N=262144.
// Table: C0:1, C1:4, C2:16, C3:64, C4:256 => 341 rows x 15 cols (padded to 16).
// R11: R3 per-thread code (best: 69.2us) + BLK=96 geometry => 6 blocks/SM,
//      576 threads/SM at NATURAL ~110 regs (no cap-induced spills).
#define NROWS 341
#define O1 1
#define O2 5
#define O3 21
#define O4 85
#define BLK 96

typedef unsigned long long u64;

__device__ __align__(16) float gC[NROWS * 16];

__device__ __forceinline__ float softplusf(float a) {
    return fmaxf(a, 0.0f) + log1pf(expf(-fabsf(a)));
}

// constrained(A): 2*(sigmoid(cumsum(softplus(A),axis=1)) - 0.5) == tanh(cumsum/2)
__global__ void prep_kernel(const float* __restrict__ A0, const float* __restrict__ A1,
                            const float* __restrict__ A2, const float* __restrict__ A3,
                            const float* __restrict__ A4) {
    int r = blockIdx.x * blockDim.x + threadIdx.x;
    if (r >= NROWS) return;
    const float* A; int lr;
    if (r < O1)      { A = A0; lr = r; }
    else if (r < O2) { A = A1; lr = r - O1; }
    else if (r < O3) { A = A2; lr = r - O2; }
    else if (r < O4) { A = A3; lr = r - O3; }
    else             { A = A4; lr = r - O4; }
    float s = 0.0f;
    #pragma unroll
    for (int t = 0; t < 15; t++) {
        s += softplusf(A[lr * 15 + t]);
        gC[r * 16 + t] = tanhf(0.5f * s);
    }
    gC[r * 16 + 15] = 0.0f;
}

// ---- f32x2 helpers ----
__device__ __forceinline__ u64 pack2(float c) {
    u64 r;
    asm("mov.b64 %0, {%1, %1};" : "=l"(r) : "r"(__float_as_uint(c)));
    return r;
}
__device__ __forceinline__ u64 pack_pair(float lo, float hi) {
    u64 r;
    asm("mov.b64 %0, {%1, %2};" : "=l"(r) : "r"(__float_as_uint(lo)), "r"(__float_as_uint(hi)));
    return r;
}
__device__ __forceinline__ void unpack2(float& lo, float& hi, u64 v) {
    unsigned a, b;
    asm("mov.b64 {%0, %1}, %2;" : "=r"(a), "=r"(b) : "l"(v));
    lo = __uint_as_float(a); hi = __uint_as_float(b);
}
__device__ __forceinline__ void ffma2(u64& d, u64 a, u64 b) {
    asm("fma.rn.f32x2 %0, %1, %2, %0;" : "+l"(d) : "l"(a), "l"(b));
}

__device__ __forceinline__ void bern3(float x, float b[4]) {
    float om = 1.0f - x;
    b[0] = om * om * om;
    b[1] = 3.0f * x * om * om;
    b[2] = 3.0f * x * x * om;
    b[3] = x * x * x;
}

// S = db[15] + sum_{t<15} tf[t]*(db[t]-db[t+1]),  db[t] = 16*C(15,t)*x^t*(1-x)^(15-t)
__device__ __forceinline__ float stage_S(const float tf[16], float xi) {
    const float comb15[16] = {1.f, 15.f, 105.f, 455.f, 1365.f, 3003.f, 5005.f, 6435.f,
                              6435.f, 5005.f, 3003.f, 1365.f, 455.f, 105.f, 15.f, 1.f};
    float db[16];
    float om = 1.0f - xi;
    float p = 16.0f;
    #pragma unroll
    for (int t = 0; t < 16; t++) { db[t] = p * comb15[t]; p *= xi; }
    p = 1.0f;
    #pragma unroll
    for (int t = 15; t >= 0; t--) { db[t] *= p; p *= om; }
    float s = db[15];
    #pragma unroll
    for (int t = 0; t < 15; t++) s = fmaf(tf[t], db[t] - db[t + 1], s);
    return s;
}

__device__ __forceinline__ float stage_S_u(const u64 t2[8], float xi) {
    float tf[16];
    #pragma unroll
    for (int i = 0; i < 8; i++) unpack2(tf[2 * i], tf[2 * i + 1], t2[i]);
    return stage_S(tf, xi);
}

// tf_a/tf_b += c_a/c_b * row[0..15]  (row: 16 floats = 8 u64, via 4x ld.shared.v2.b64)
__device__ __forceinline__ void acc_row2(u64 tfa[8], u64 tfb[8], float ca, float cb,
                                         const float* __restrict__ row) {
    u64 r0, r1, r2, r3, r4, r5, r6, r7;
    size_t p = __cvta_generic_to_shared(row);
    asm("ld.shared.v2.b64 {%0, %1}, [%2];"      : "=l"(r0), "=l"(r1) : "l"(p));
    asm("ld.shared.v2.b64 {%0, %1}, [%2 + 16];" : "=l"(r2), "=l"(r3) : "l"(p));
    asm("ld.shared.v2.b64 {%0, %1}, [%2 + 32];" : "=l"(r4), "=l"(r5) : "l"(p));
    asm("ld.shared.v2.b64 {%0, %1}, [%2 + 48];" : "=l"(r6), "=l"(r7) : "l"(p));
    u64 cca = pack2(ca), ccb = pack2(cb);
    ffma2(tfa[0], cca, r0); ffma2(tfa[1], cca, r1);
    ffma2(tfa[2], cca, r2); ffma2(tfa[3], cca, r3);
    ffma2(tfa[4], cca, r4); ffma2(tfa[5], cca, r5);
    ffma2(tfa[6], cca, r6); ffma2(tfa[7], cca, r7);
    ffma2(tfb[0], ccb, r0); ffma2(tfb[1], ccb, r1);
    ffma2(tfb[2], ccb, r2); ffma2(tfb[3], ccb, r3);
    ffma2(tfb[4], ccb, r4); ffma2(tfb[5], ccb, r5);
    ffma2(tfb[6], ccb, r6); ffma2(tfb[7], ccb, r7);
}

__global__ __launch_bounds__(BLK, 6)
void bflow_kernel(const float* __restrict__ x, float* __restrict__ out, int n) {
    __shared__ __align__(16) float sC[NROWS * 16];
    __shared__ u64 sCB2[16][BLK];   // packed (cb2 of point a, cb2 of point b)

    {   // stage the coefficient table into SMEM
        const float4* src = (const float4*)gC;
        float4* dst = (float4*)sC;
        for (int i = threadIdx.x; i < NROWS * 4; i += BLK) dst[i] = src[i];
    }
    __syncthreads();

    int base = blockIdx.x * (BLK * 2);
    int ia = base + threadIdx.x;
    int ib = ia + BLK;
    bool va = ia < n, vb = ib < n;
    int ra = va ? ia : 0, rb = vb ? ib : 0;

    float xa[5], xb[5];
    #pragma unroll
    for (int j = 0; j < 5; j++) { xa[j] = x[ra * 5 + j]; xb[j] = x[rb * 5 + j]; }

    float dens_a, dens_b;
    u64 ta[8], tb[8];

    // ---- stage 0: cb = [1] (same tf for both points) ----
    {
        float tf[16];
        #pragma unroll
        for (int t = 0; t < 16; t++) tf[t] = sC[t];
        dens_a = stage_S(tf, xa[0]);
        dens_b = stage_S(tf, xb[0]);
    }

    float Ba0[4], Bb0[4]; bern3(xa[0], Ba0); bern3(xb[0], Bb0);

    // ---- stage 1: cb = B0 ----
    #pragma unroll
    for (int i = 0; i < 8; i++) { ta[i] = 0ull; tb[i] = 0ull; }
    #pragma unroll
    for (int k = 0; k < 4; k++)
        acc_row2(ta, tb, Ba0[k], Bb0[k], sC + (O1 + k) * 16);
    dens_a *= stage_S_u(ta, xa[1]);
    dens_b *= stage_S_u(tb, xb[1]);

    float Ba1[4], Bb1[4]; bern3(xa[1], Ba1); bern3(xb[1], Bb1);

    // ---- stage 2: cb2 = B0 (x) B1; also store packed cb2 to SMEM ----
    #pragma unroll
    for (int i = 0; i < 8; i++) { ta[i] = 0ull; tb[i] = 0ull; }
    #pragma unroll
    for (int m = 0; m < 4; m++)
        #pragma unroll
        for (int k = 0; k < 4; k++) {
            float c2a = Ba0[m] * Ba1[k];
            float c2b = Bb0[m] * Bb1[k];
            sCB2[m * 4 + k][threadIdx.x] = pack_pair(c2a, c2b);
            acc_row2(ta, tb, c2a, c2b, sC + (O2 + m * 4 + k) * 16);
        }
    dens_a *= stage_S_u(ta, xa[2]);
    dens_b *= stage_S_u(tb, xb[2]);

    float Ba2[4], Bb2[4]; bern3(xa[2], Ba2); bern3(xb[2], Bb2);

    // ---- stage 3: cb3[m*4+k] = cb2[m]*B2[k], rolled outer loop ----
    #pragma unroll
    for (int i = 0; i < 8; i++) { ta[i] = 0ull; tb[i] = 0ull; }
    #pragma unroll 1
    for (int m = 0; m < 16; m++) {
        float c2a, c2b; unpack2(c2a, c2b, sCB2[m][threadIdx.x]);
        const float* bp = sC + (O3 + m * 4) * 16;
        #pragma unroll
        for (int k = 0; k < 4; k++)
            acc_row2(ta, tb, c2a * Ba2[k], c2b * Bb2[k], bp + k * 16);
    }
    dens_a *= stage_S_u(ta, xa[3]);
    dens_b *= stage_S_u(tb, xb[3]);

    float Ba3[4], Bb3[4]; bern3(xa[3], Ba3); bern3(xb[3], Bb3);

    // ---- stage 4: cb4[(m*4+k2)*4+k3] = cb2[m]*B2[k2]*B3[k3], rolled outer loop ----
    #pragma unroll
    for (int i = 0; i < 8; i++) { ta[i] = 0ull; tb[i] = 0ull; }
    #pragma unroll 1
    for (int m = 0; m < 16; m++) {
        float c2a, c2b; unpack2(c2a, c2b, sCB2[m][threadIdx.x]);
        const float* bp = sC + (O4 + m * 16) * 16;
        #pragma unroll
        for (int k2 = 0; k2 < 4; k2++) {
            float c3a = c2a * Ba2[k2];
            float c3b = c2b * Bb2[k2];
            #pragma unroll
            for (int k3 = 0; k3 < 4; k3++)
                acc_row2(ta, tb, c3a * Ba3[k3], c3b * Bb3[k3], bp + (k2 * 4 + k3) * 16);
        }
    }
    dens_a *= stage_S_u(ta, xa[4]);
    dens_b *= stage_S_u(tb, xb[4]);

    if (va) out[ia] = dens_a;
    if (vb) out[ib] = dens_b;
}

extern "C" void kernel_launch(void* const* d_in, const int* in_sizes, int n_in,
                              void* d_out, int out_size) {
    const float* x  = (const float*)d_in[0];
    const float* A0 = (const float*)d_in[1];
    const float* A1 = (const float*)d_in[2];
    const float* A2 = (const float*)d_in[3];
    const float* A3 = (const float*)d_in[4];
    const float* A4 = (const float*)d_in[5];
    float* out = (float*)d_out;
    int n = in_sizes[0] / 5;

    prep_kernel<<<(NROWS + 127) / 128, 128>>>(A0, A1, A2, A3, A4);
    int pts_per_blk = BLK * 2;
    bflow_kernel<<<(n + pts_per_blk - 1) / pts_per_blk, BLK>>>(x, out, n);
}

// round 15
// speedup vs baseline: 1.4900x; 1.0596x over previous
#include <cuda_runtime.h>

// Bernstein flow density, DIM=5, TF_DEG=16, COND_DEG=3, N=262144.
// Table: C0:1, C1:4, C2:16, C3:64, C4:256 => 341 rows x 15 cols (padded to 16).
// R13: R3 config (BLK=128, plain launch_bounds -> natural regs, 4 blocks/SM)
//      + packed f32x2 coefficient chains in stages 3/4 (-6.8% instrs).
#define NROWS 341
#define O1 1
#define O2 5
#define O3 21
#define O4 85
#define BLK 128

typedef unsigned long long u64;

__device__ __align__(16) float gC[NROWS * 16];

__device__ __forceinline__ float softplusf(float a) {
    return fmaxf(a, 0.0f) + log1pf(expf(-fabsf(a)));
}

// constrained(A): 2*(sigmoid(cumsum(softplus(A),axis=1)) - 0.5) == tanh(cumsum/2)
__global__ void prep_kernel(const float* __restrict__ A0, const float* __restrict__ A1,
                            const float* __restrict__ A2, const float* __restrict__ A3,
                            const float* __restrict__ A4) {
    int r = blockIdx.x * blockDim.x + threadIdx.x;
    if (r >= NROWS) return;
    const float* A; int lr;
    if (r < O1)      { A = A0; lr = r; }
    else if (r < O2) { A = A1; lr = r - O1; }
    else if (r < O3) { A = A2; lr = r - O2; }
    else if (r < O4) { A = A3; lr = r - O3; }
    else             { A = A4; lr = r - O4; }
    float s = 0.0f;
    #pragma unroll
    for (int t = 0; t < 15; t++) {
        s += softplusf(A[lr * 15 + t]);
        gC[r * 16 + t] = tanhf(0.5f * s);
    }
    gC[r * 16 + 15] = 0.0f;
}

// ---- f32x2 helpers ----
__device__ __forceinline__ u64 pack2(float c) {
    u64 r;
    asm("mov.b64 %0, {%1, %1};" : "=l"(r) : "r"(__float_as_uint(c)));
    return r;
}
__device__ __forceinline__ u64 pack_pair(float lo, float hi) {
    u64 r;
    asm("mov.b64 %0, {%1, %2};" : "=l"(r) : "r"(__float_as_uint(lo)), "r"(__float_as_uint(hi)));
    return r;
}
__device__ __forceinline__ void unpack2(float& lo, float& hi, u64 v) {
    unsigned a, b;
    asm("mov.b64 {%0, %1}, %2;" : "=r"(a), "=r"(b) : "l"(v));
    lo = __uint_as_float(a); hi = __uint_as_float(b);
}
__device__ __forceinline__ void ffma2(u64& d, u64 a, u64 b) {
    asm("fma.rn.f32x2 %0, %1, %2, %0;" : "+l"(d) : "l"(a), "l"(b));
}
__device__ __forceinline__ u64 mulx2(u64 a, u64 b) {
    u64 r;
    asm("mul.rn.f32x2 %0, %1, %2;" : "=l"(r) : "l"(a), "l"(b));
    return r;
}

__device__ __forceinline__ void bern3(float x, float b[4]) {
    float om = 1.0f - x;
    b[0] = om * om * om;
    b[1] = 3.0f * x * om * om;
    b[2] = 3.0f * x * x * om;
    b[3] = x * x * x;
}

// S = db[15] + sum_{t<15} tf[t]*(db[t]-db[t+1]),  db[t] = 16*C(15,t)*x^t*(1-x)^(15-t)
__device__ __forceinline__ float stage_S(const float tf[16], float xi) {
    const float comb15[16] = {1.f, 15.f, 105.f, 455.f, 1365.f, 3003.f, 5005.f, 6435.f,
                              6435.f, 5005.f, 3003.f, 1365.f, 455.f, 105.f, 15.f, 1.f};
    float db[16];
    float om = 1.0f - xi;
    float p = 16.0f;
    #pragma unroll
    for (int t = 0; t < 16; t++) { db[t] = p * comb15[t]; p *= xi; }
    p = 1.0f;
    #pragma unroll
    for (int t = 15; t >= 0; t--) { db[t] *= p; p *= om; }
    float s = db[15];
    #pragma unroll
    for (int t = 0; t < 15; t++) s = fmaf(tf[t], db[t] - db[t + 1], s);
    return s;
}

__device__ __forceinline__ float stage_S_u(const u64 t2[8], float xi) {
    float tf[16];
    #pragma unroll
    for (int i = 0; i < 8; i++) unpack2(tf[2 * i], tf[2 * i + 1], t2[i]);
    return stage_S(tf, xi);
}

// tfa/tfb += cca/ccb * row[0..15]; cca/ccb are duplicated-pair (c,c) u64.
__device__ __forceinline__ void acc_row2(u64 tfa[8], u64 tfb[8], u64 cca, u64 ccb,
                                         const float* __restrict__ row) {
    u64 r0, r1, r2, r3, r4, r5, r6, r7;
    size_t p = __cvta_generic_to_shared(row);
    asm("ld.shared.v2.b64 {%0, %1}, [%2];"      : "=l"(r0), "=l"(r1) : "l"(p));
    asm("ld.shared.v2.b64 {%0, %1}, [%2 + 16];" : "=l"(r2), "=l"(r3) : "l"(p));
    asm("ld.shared.v2.b64 {%0, %1}, [%2 + 32];" : "=l"(r4), "=l"(r5) : "l"(p));
    asm("ld.shared.v2.b64 {%0, %1}, [%2 + 48];" : "=l"(r6), "=l"(r7) : "l"(p));
    ffma2(tfa[0], cca, r0); ffma2(tfa[1], cca, r1);
    ffma2(tfa[2], cca, r2); ffma2(tfa[3], cca, r3);
    ffma2(tfa[4], cca, r4); ffma2(tfa[5], cca, r5);
    ffma2(tfa[6], cca, r6); ffma2(tfa[7], cca, r7);
    ffma2(tfb[0], ccb, r0); ffma2(tfb[1], ccb, r1);
    ffma2(tfb[2], ccb, r2); ffma2(tfb[3], ccb, r3);
    ffma2(tfb[4], ccb, r4); ffma2(tfb[5], ccb, r5);
    ffma2(tfb[6], ccb, r6); ffma2(tfb[7], ccb, r7);
}

__global__ __launch_bounds__(BLK)
void bflow_kernel(const float* __restrict__ x, float* __restrict__ out, int n) {
    __shared__ __align__(16) float sC[NROWS * 16];
    __shared__ u64 sCB2[16][BLK];   // packed (cb2_a, cb2_b) per thread

    {   // stage the coefficient table into SMEM
        const float4* src = (const float4*)gC;
        float4* dst = (float4*)sC;
        for (int i = threadIdx.x; i < NROWS * 4; i += BLK) dst[i] = src[i];
    }
    __syncthreads();

    int base = blockIdx.x * (BLK * 2);
    int ia = base + threadIdx.x;
    int ib = ia + BLK;
    bool va = ia < n, vb = ib < n;
    int ra = va ? ia : 0, rb = vb ? ib : 0;

    float xa[5], xb[5];
    #pragma unroll
    for (int j = 0; j < 5; j++) { xa[j] = x[ra * 5 + j]; xb[j] = x[rb * 5 + j]; }

    float dens_a, dens_b;
    u64 ta[8], tb[8];

    // ---- stage 0: cb = [1] (same tf for both points) ----
    {
        float tf[16];
        #pragma unroll
        for (int t = 0; t < 16; t++) tf[t] = sC[t];
        dens_a = stage_S(tf, xa[0]);
        dens_b = stage_S(tf, xb[0]);
    }

    float Ba0[4], Bb0[4]; bern3(xa[0], Ba0); bern3(xb[0], Bb0);

    // ---- stage 1: cb = B0 ----
    #pragma unroll
    for (int i = 0; i < 8; i++) { ta[i] = 0ull; tb[i] = 0ull; }
    #pragma unroll
    for (int k = 0; k < 4; k++)
        acc_row2(ta, tb, pack2(Ba0[k]), pack2(Bb0[k]), sC + (O1 + k) * 16);
    dens_a *= stage_S_u(ta, xa[1]);
    dens_b *= stage_S_u(tb, xb[1]);

    float Ba1[4], Bb1[4]; bern3(xa[1], Ba1); bern3(xb[1], Bb1);

    // ---- stage 2: cb2 = B0 (x) B1; also store packed cb2 to SMEM ----
    #pragma unroll
    for (int i = 0; i < 8; i++) { ta[i] = 0ull; tb[i] = 0ull; }
    #pragma unroll
    for (int m = 0; m < 4; m++)
        #pragma unroll
        for (int k = 0; k < 4; k++) {
            float c2a = Ba0[m] * Ba1[k];
            float c2b = Bb0[m] * Bb1[k];
            sCB2[m * 4 + k][threadIdx.x] = pack_pair(c2a, c2b);
            acc_row2(ta, tb, pack2(c2a), pack2(c2b), sC + (O2 + m * 4 + k) * 16);
        }
    dens_a *= stage_S_u(ta, xa[2]);
    dens_b *= stage_S_u(tb, xb[2]);

    // Packed Bernstein factors for dims 2 and 3 (duplicated pairs).
    u64 Ba2d[4], Bb2d[4];
    {
        float Ba2[4], Bb2[4]; bern3(xa[2], Ba2); bern3(xb[2], Bb2);
        #pragma unroll
        for (int k = 0; k < 4; k++) { Ba2d[k] = pack2(Ba2[k]); Bb2d[k] = pack2(Bb2[k]); }
    }

    // ---- stage 3: cb3[m*4+k] = cb2[m]*B2[k], rolled outer loop ----
    #pragma unroll
    for (int i = 0; i < 8; i++) { ta[i] = 0ull; tb[i] = 0ull; }
    #pragma unroll 1
    for (int m = 0; m < 16; m++) {
        float c2a, c2b; unpack2(c2a, c2b, sCB2[m][threadIdx.x]);
        u64 c2ad = pack2(c2a), c2bd = pack2(c2b);
        const float* bp = sC + (O3 + m * 4) * 16;
        #pragma unroll
        for (int k = 0; k < 4; k++)
            acc_row2(ta, tb, mulx2(c2ad, Ba2d[k]), mulx2(c2bd, Bb2d[k]), bp + k * 16);
    }
    dens_a *= stage_S_u(ta, xa[3]);
    dens_b *= stage_S_u(tb, xb[3]);

    u64 Ba3d[4], Bb3d[4];
    {
        float Ba3[4], Bb3[4]; bern3(xa[3], Ba3); bern3(xb[3], Bb3);
        #pragma unroll
        for (int k = 0; k < 4; k++) { Ba3d[k] = pack2(Ba3[k]); Bb3d[k] = pack2(Bb3[k]); }
    }

    // ---- stage 4: cb4[(m*4+k2)*4+k3] = cb2[m]*B2[k2]*B3[k3], rolled outer loop ----
    #pragma unroll
    for (int i = 0; i < 8; i++) { ta[i] = 0ull; tb[i] = 0ull; }
    #pragma unroll 1
    for (int m = 0; m < 16; m++) {
        float c2a, c2b; unpack2(c2a, c2b, sCB2[m][threadIdx.x]);
        u64 c2ad = pack2(c2a), c2bd = pack2(c2b);
        const float* bp = sC + (O4 + m * 16) * 16;
        #pragma unroll
        for (int k2 = 0; k2 < 4; k2++) {
            u64 c3ad = mulx2(c2ad, Ba2d[k2]);
            u64 c3bd = mulx2(c2bd, Bb2d[k2]);
            #pragma unroll
            for (int k3 = 0; k3 < 4; k3++)
                acc_row2(ta, tb, mulx2(c3ad, Ba3d[k3]), mulx2(c3bd, Bb3d[k3]),
                         bp + (k2 * 4 + k3) * 16);
        }
    }
    dens_a *= stage_S_u(ta, xa[4]);
    dens_b *= stage_S_u(tb, xb[4]);

    if (va) out[ia] = dens_a;
    if (vb) out[ib] = dens_b;
}

extern "C" void kernel_launch(void* const* d_in, const int* in_sizes, int n_in,
                              void* d_out, int out_size) {
    const float* x  = (const float*)d_in[0];
    const float* A0 = (const float*)d_in[1];
    const float* A1 = (const float*)d_in[2];
    const float* A2 = (const float*)d_in[3];
    const float* A3 = (const float*)d_in[4];
    const float* A4 = (const float*)d_in[5];
    float* out = (float*)d_out;
    int n = in_sizes[0] / 5;

    prep_kernel<<<(NROWS + 127) / 128, 128>>>(A0, A1, A2, A3, A4);
    int pts_per_blk = BLK * 2;
    bflow_kernel<<<(n + pts_per_blk - 1) / pts_per_blk, BLK>>>(x, out, n);
}

// round 17
// speedup vs baseline: 1.6235x; 1.0896x over previous
#include <cuda_runtime.h>

// Bernstein flow density, DIM=5, TF_DEG=16, COND_DEG=3, N=262144.
// Table: C0:1, C1:4, C2:16, C3:64, C4:256 => 341 rows x 15 cols (padded to 16).
// R16: exact R3 code (best: 69.2us) with stage-3/4 m-loops at unroll 2
//      (cross-iteration ILP to fill FFMA2 gap slots at m boundaries).
#define NROWS 341
#define O1 1
#define O2 5
#define O3 21
#define O4 85
#define BLK 128

typedef unsigned long long u64;

__device__ __align__(16) float gC[NROWS * 16];

__device__ __forceinline__ float softplusf(float a) {
    return fmaxf(a, 0.0f) + log1pf(expf(-fabsf(a)));
}

// constrained(A): 2*(sigmoid(cumsum(softplus(A),axis=1)) - 0.5) == tanh(cumsum/2)
__global__ void prep_kernel(const float* __restrict__ A0, const float* __restrict__ A1,
                            const float* __restrict__ A2, const float* __restrict__ A3,
                            const float* __restrict__ A4) {
    int r = blockIdx.x * blockDim.x + threadIdx.x;
    if (r >= NROWS) return;
    const float* A; int lr;
    if (r < O1)      { A = A0; lr = r; }
    else if (r < O2) { A = A1; lr = r - O1; }
    else if (r < O3) { A = A2; lr = r - O2; }
    else if (r < O4) { A = A3; lr = r - O3; }
    else             { A = A4; lr = r - O4; }
    float s = 0.0f;
    #pragma unroll
    for (int t = 0; t < 15; t++) {
        s += softplusf(A[lr * 15 + t]);
        gC[r * 16 + t] = tanhf(0.5f * s);
    }
    gC[r * 16 + 15] = 0.0f;
}

// ---- f32x2 helpers ----
__device__ __forceinline__ u64 pack2(float c) {
    u64 r;
    asm("mov.b64 %0, {%1, %1};" : "=l"(r) : "r"(__float_as_uint(c)));
    return r;
}
__device__ __forceinline__ u64 pack_pair(float lo, float hi) {
    u64 r;
    asm("mov.b64 %0, {%1, %2};" : "=l"(r) : "r"(__float_as_uint(lo)), "r"(__float_as_uint(hi)));
    return r;
}
__device__ __forceinline__ void unpack2(float& lo, float& hi, u64 v) {
    unsigned a, b;
    asm("mov.b64 {%0, %1}, %2;" : "=r"(a), "=r"(b) : "l"(v));
    lo = __uint_as_float(a); hi = __uint_as_float(b);
}
__device__ __forceinline__ void ffma2(u64& d, u64 a, u64 b) {
    asm("fma.rn.f32x2 %0, %1, %2, %0;" : "+l"(d) : "l"(a), "l"(b));
}

__device__ __forceinline__ void bern3(float x, float b[4]) {
    float om = 1.0f - x;
    b[0] = om * om * om;
    b[1] = 3.0f * x * om * om;
    b[2] = 3.0f * x * x * om;
    b[3] = x * x * x;
}

// S = db[15] + sum_{t<15} tf[t]*(db[t]-db[t+1]),  db[t] = 16*C(15,t)*x^t*(1-x)^(15-t)
__device__ __forceinline__ float stage_S(const float tf[16], float xi) {
    const float comb15[16] = {1.f, 15.f, 105.f, 455.f, 1365.f, 3003.f, 5005.f, 6435.f,
                              6435.f, 5005.f, 3003.f, 1365.f, 455.f, 105.f, 15.f, 1.f};
    float db[16];
    float om = 1.0f - xi;
    float p = 16.0f;
    #pragma unroll
    for (int t = 0; t < 16; t++) { db[t] = p * comb15[t]; p *= xi; }
    p = 1.0f;
    #pragma unroll
    for (int t = 15; t >= 0; t--) { db[t] *= p; p *= om; }
    float s = db[15];
    #pragma unroll
    for (int t = 0; t < 15; t++) s = fmaf(tf[t], db[t] - db[t + 1], s);
    return s;
}

__device__ __forceinline__ float stage_S_u(const u64 t2[8], float xi) {
    float tf[16];
    #pragma unroll
    for (int i = 0; i < 8; i++) unpack2(tf[2 * i], tf[2 * i + 1], t2[i]);
    return stage_S(tf, xi);
}

// tf_a/tf_b += c_a/c_b * row[0..15]  (row: 16 floats = 8 u64, via 4x ld.shared.v2.b64)
__device__ __forceinline__ void acc_row2(u64 tfa[8], u64 tfb[8], float ca, float cb,
                                         const float* __restrict__ row) {
    u64 r0, r1, r2, r3, r4, r5, r6, r7;
    size_t p = __cvta_generic_to_shared(row);
    asm("ld.shared.v2.b64 {%0, %1}, [%2];"      : "=l"(r0), "=l"(r1) : "l"(p));
    asm("ld.shared.v2.b64 {%0, %1}, [%2 + 16];" : "=l"(r2), "=l"(r3) : "l"(p));
    asm("ld.shared.v2.b64 {%0, %1}, [%2 + 32];" : "=l"(r4), "=l"(r5) : "l"(p));
    asm("ld.shared.v2.b64 {%0, %1}, [%2 + 48];" : "=l"(r6), "=l"(r7) : "l"(p));
    u64 cca = pack2(ca), ccb = pack2(cb);
    ffma2(tfa[0], cca, r0); ffma2(tfa[1], cca, r1);
    ffma2(tfa[2], cca, r2); ffma2(tfa[3], cca, r3);
    ffma2(tfa[4], cca, r4); ffma2(tfa[5], cca, r5);
    ffma2(tfa[6], cca, r6); ffma2(tfa[7], cca, r7);
    ffma2(tfb[0], ccb, r0); ffma2(tfb[1], ccb, r1);
    ffma2(tfb[2], ccb, r2); ffma2(tfb[3], ccb, r3);
    ffma2(tfb[4], ccb, r4); ffma2(tfb[5], ccb, r5);
    ffma2(tfb[6], ccb, r6); ffma2(tfb[7], ccb, r7);
}

__global__ __launch_bounds__(BLK)
void bflow_kernel(const float* __restrict__ x, float* __restrict__ out, int n) {
    __shared__ __align__(16) float sC[NROWS * 16];
    __shared__ u64 sCB2[16][BLK];   // packed (cb2 of point a, cb2 of point b)

    {   // stage the coefficient table into SMEM
        const float4* src = (const float4*)gC;
        float4* dst = (float4*)sC;
        for (int i = threadIdx.x; i < NROWS * 4; i += BLK) dst[i] = src[i];
    }
    __syncthreads();

    int base = blockIdx.x * (BLK * 2);
    int ia = base + threadIdx.x;
    int ib = ia + BLK;
    bool va = ia < n, vb = ib < n;
    int ra = va ? ia : 0, rb = vb ? ib : 0;

    float xa[5], xb[5];
    #pragma unroll
    for (int j = 0; j < 5; j++) { xa[j] = x[ra * 5 + j]; xb[j] = x[rb * 5 + j]; }

    float dens_a, dens_b;
    u64 ta[8], tb[8];

    // ---- stage 0: cb = [1] (same tf for both points) ----
    {
        float tf[16];
        #pragma unroll
        for (int t = 0; t < 16; t++) tf[t] = sC[t];
        dens_a = stage_S(tf, xa[0]);
        dens_b = stage_S(tf, xb[0]);
    }

    float Ba0[4], Bb0[4]; bern3(xa[0], Ba0); bern3(xb[0], Bb0);

    // ---- stage 1: cb = B0 ----
    #pragma unroll
    for (int i = 0; i < 8; i++) { ta[i] = 0ull; tb[i] = 0ull; }
    #pragma unroll
    for (int k = 0; k < 4; k++)
        acc_row2(ta, tb, Ba0[k], Bb0[k], sC + (O1 + k) * 16);
    dens_a *= stage_S_u(ta, xa[1]);
    dens_b *= stage_S_u(tb, xb[1]);

    float Ba1[4], Bb1[4]; bern3(xa[1], Ba1); bern3(xb[1], Bb1);

    // ---- stage 2: cb2 = B0 (x) B1; also store packed cb2 to SMEM ----
    #pragma unroll
    for (int i = 0; i < 8; i++) { ta[i] = 0ull; tb[i] = 0ull; }
    #pragma unroll
    for (int m = 0; m < 4; m++)
        #pragma unroll
        for (int k = 0; k < 4; k++) {
            float c2a = Ba0[m] * Ba1[k];
            float c2b = Bb0[m] * Bb1[k];
            sCB2[m * 4 + k][threadIdx.x] = pack_pair(c2a, c2b);
            acc_row2(ta, tb, c2a, c2b, sC + (O2 + m * 4 + k) * 16);
        }
    dens_a *= stage_S_u(ta, xa[2]);
    dens_b *= stage_S_u(tb, xb[2]);

    float Ba2[4], Bb2[4]; bern3(xa[2], Ba2); bern3(xb[2], Bb2);

    // ---- stage 3: cb3[m*4+k] = cb2[m]*B2[k], unroll 2 for cross-iter ILP ----
    #pragma unroll
    for (int i = 0; i < 8; i++) { ta[i] = 0ull; tb[i] = 0ull; }
    #pragma unroll 2
    for (int m = 0; m < 16; m++) {
        float c2a, c2b; unpack2(c2a, c2b, sCB2[m][threadIdx.x]);
        const float* bp = sC + (O3 + m * 4) * 16;
        #pragma unroll
        for (int k = 0; k < 4; k++)
            acc_row2(ta, tb, c2a * Ba2[k], c2b * Bb2[k], bp + k * 16);
    }
    dens_a *= stage_S_u(ta, xa[3]);
    dens_b *= stage_S_u(tb, xb[3]);

    float Ba3[4], Bb3[4]; bern3(xa[3], Ba3); bern3(xb[3], Bb3);

    // ---- stage 4: cb4[(m*4+k2)*4+k3] = cb2[m]*B2[k2]*B3[k3], unroll 2 ----
    #pragma unroll
    for (int i = 0; i < 8; i++) { ta[i] = 0ull; tb[i] = 0ull; }
    #pragma unroll 2
    for (int m = 0; m < 16; m++) {
        float c2a, c2b; unpack2(c2a, c2b, sCB2[m][threadIdx.x]);
        const float* bp = sC + (O4 + m * 16) * 16;
        #pragma unroll
        for (int k2 = 0; k2 < 4; k2++) {
            float c3a = c2a * Ba2[k2];
            float c3b = c2b * Bb2[k2];
            #pragma unroll
            for (int k3 = 0; k3 < 4; k3++)
                acc_row2(ta, tb, c3a * Ba3[k3], c3b * Bb3[k3], bp + (k2 * 4 + k3) * 16);
        }
    }
    dens_a *= stage_S_u(ta, xa[4]);
    dens_b *= stage_S_u(tb, xb[4]);

    if (va) out[ia] = dens_a;
    if (vb) out[ib] = dens_b;
}

extern "C" void kernel_launch(void* const* d_in, const int* in_sizes, int n_in,
                              void* d_out, int out_size) {
    const float* x  = (const float*)d_in[0];
    const float* A0 = (const float*)d_in[1];
    const float* A1 = (const float*)d_in[2];
    const float* A2 = (const float*)d_in[3];
    const float* A3 = (const float*)d_in[4];
    const float* A4 = (const float*)d_in[5];
    float* out = (float*)d_out;
    int n = in_sizes[0] / 5;

    prep_kernel<<<(NROWS + 127) / 128, 128>>>(A0, A1, A2, A3, A4);
    int pts_per_blk = BLK * 2;
    bflow_kernel<<<(n + pts_per_blk - 1) / pts_per_blk, BLK>>>(x, out, n);
}